// round 5
// baseline (speedup 1.0000x reference)
#include <cuda_runtime.h>
#include <cuda_fp16.h>
#include <stdint.h>

// Shapes (fixed): x [B=256, N=196, C=768], weight [C=768, N=196], y [B, N, C]
#define NREAL  196
#define CDIM   768
#define KPAD   208        // n and k_dct padded to 13*16
#define KSTEPS 13
#define MC     128        // channels per tile
#define NTILES 1536       // 256 batches * 6 channel-blocks
#define GRID   148        // persistent

#define XPITCHB 272       // X row pitch bytes (136 halfs; 272%128=16 -> conflict-free trans)
#define TPITCHB 432       // T row pitch bytes (216 halfs; 432%128=48 -> conflict-free)
#define BPITCH  200       // B1 pitch halfs (400B; 400%128=16 -> conflict-free both)
#define WPITCH  208

#define SM_B1  0                      // 208*200*2 = 83,200
#define SM_P0  83200                  // 56,576 (X: 208x136 halfs; T: 128x216 halfs)
#define SM_P1  139776                 // 56,576
#define PBYTES 56576
#define SMEM_TOTAL 196352
#define NF4    6272                   // float4 per X tile (196 rows * 32)

__device__ __align__(16) __half g_B1[KPAD * BPITCH];   // B1[n][k] = 2*cos(pi*k*(2n+1)/(2N))
__device__ __align__(16) __half g_wh2[CDIM * WPITCH];  // w[c][k] * s_k, zero-padded

// ---------------- helpers ----------------
__device__ __forceinline__ uint32_t smem_u32(const void* p) {
    uint32_t a;
    asm("{ .reg .u64 t; cvta.to.shared.u64 t, %1; cvt.u32.u64 %0, t; }" : "=r"(a) : "l"(p));
    return a;
}
__device__ __forceinline__ void ldsm_x4(uint32_t addr, uint32_t& r0, uint32_t& r1,
                                        uint32_t& r2, uint32_t& r3) {
    asm volatile("ldmatrix.sync.aligned.m8n8.x4.shared.b16 {%0,%1,%2,%3}, [%4];"
                 : "=r"(r0), "=r"(r1), "=r"(r2), "=r"(r3) : "r"(addr));
}
__device__ __forceinline__ void ldsm_x2(uint32_t addr, uint32_t& r0, uint32_t& r1) {
    asm volatile("ldmatrix.sync.aligned.m8n8.x2.shared.b16 {%0,%1}, [%2];"
                 : "=r"(r0), "=r"(r1) : "r"(addr));
}
__device__ __forceinline__ void ldsm_x4t(uint32_t addr, uint32_t& r0, uint32_t& r1,
                                         uint32_t& r2, uint32_t& r3) {
    asm volatile("ldmatrix.sync.aligned.m8n8.x4.trans.shared.b16 {%0,%1,%2,%3}, [%4];"
                 : "=r"(r0), "=r"(r1), "=r"(r2), "=r"(r3) : "r"(addr));
}
__device__ __forceinline__ void ldsm_x2t(uint32_t addr, uint32_t& r0, uint32_t& r1) {
    asm volatile("ldmatrix.sync.aligned.m8n8.x2.trans.shared.b16 {%0,%1}, [%2];"
                 : "=r"(r0), "=r"(r1) : "r"(addr));
}
__device__ __forceinline__ void mma16816(float c[4], uint32_t a0, uint32_t a1, uint32_t a2,
                                         uint32_t a3, uint32_t b0, uint32_t b1) {
    asm volatile(
        "mma.sync.aligned.m16n8k16.row.col.f32.f16.f16.f32 "
        "{%0,%1,%2,%3}, {%4,%5,%6,%7}, {%8,%9}, {%0,%1,%2,%3};"
        : "+f"(c[0]), "+f"(c[1]), "+f"(c[2]), "+f"(c[3])
        : "r"(a0), "r"(a1), "r"(a2), "r"(a3), "r"(b0), "r"(b1));
}
__device__ __forceinline__ void xstore(char* dst, int pfi, float4 v) {
    __half2 h0 = __floats2half2_rn(v.x, v.y);
    __half2 h1 = __floats2half2_rn(v.z, v.w);
    uint2 u = make_uint2(*(uint32_t*)&h0, *(uint32_t*)&h1);
    *(uint2*)(dst + (pfi >> 5) * XPITCHB + (pfi & 31) * 8) = u;
}

// ---------------- fused setup ----------------
__global__ void setup_all(const float* __restrict__ w) {
    int r = blockIdx.x;    // 0..767
    int k = threadIdx.x;   // 0..207
    float s = (k == 0) ? (0.25f / NREAL) : ((k < NREAL) ? (0.5f / NREAL) : 0.f);
    float wv = (k < NREAL) ? w[(size_t)r * NREAL + k] : 0.f;
    g_wh2[r * WPITCH + k] = __float2half_rn(wv * s);
    if (r < KPAD && k < BPITCH) {
        float v = 0.f;
        if (r < NREAL && k < NREAL) {
            int rr = (k * (2 * r + 1)) % (4 * NREAL);
            v = 2.f * cospif((float)rr / (float)(2 * NREAL));
        }
        g_B1[r * BPITCH + k] = __float2half_rn(v);
    }
}

// ---------------- main persistent kernel ----------------
__global__ __launch_bounds__(256, 1)
void dct_mma_kernel(const float* __restrict__ x, float* __restrict__ y) {
    extern __shared__ __align__(16) char smem[];
    const uint32_t sb = smem_u32(smem);
    const uint32_t sB = sb + SM_B1;
    const int tid = threadIdx.x;
    const int lane = tid & 31, wid = tid >> 5;
    const int mw = wid & 3;              // 4 M-groups of 32 channels
    const int nw = wid >> 2;             // 2 N-groups of 104
    const int cw = mw * 32;
    const int nbase = nw * 104;

    const int lr  = lane & 15;
    const int lc  = lane >> 4;
    const int kk  = (lane & 7) + ((lane >> 4) << 3);
    const int g8  = ((lane >> 3) & 1) << 3;
    const int grp = lane >> 2;
    const int q2  = (lane & 3) << 1;

    // One-time: copy B1, zero both P buffers (incl. X pad rows).
    {
        const float4* s1 = (const float4*)g_B1;
        float4* d1 = (float4*)(smem + SM_B1);
        for (int i = tid; i < (KPAD * BPITCH * 2) / 16; i += 256) d1[i] = s1[i];
        float4 z = make_float4(0.f, 0.f, 0.f, 0.f);
        float4* pz = (float4*)(smem + SM_P0);
        for (int i = tid; i < (2 * PBYTES) / 16; i += 256) pz[i] = z;
    }

    // Prologue: blocking load of first tile into P0.
    int t = blockIdx.x;
    __syncthreads();
    {
        const float4* xp = (const float4*)(x + (size_t)(t / 6) * NREAL * CDIM + (t % 6) * MC);
        char* dst = smem + SM_P0;
        for (int i = tid; i < NF4; i += 256)
            xstore(dst, i, xp[(i >> 5) * (CDIM / 4) + (i & 31)]);
    }
    __syncthreads();

    int it = 0;
    for (; t < NTILES; t += GRID, it ^= 1) {
        const int c0 = (t % 6) * MC;
        const int b  = t / 6;
        char* Pa = smem + (it ? SM_P1 : SM_P0);
        char* Pb = smem + (it ? SM_P0 : SM_P1);
        const uint32_t sPa = sb + (it ? SM_P1 : SM_P0);

        const int t2 = t + GRID;
        const bool pfv = (t2 < NTILES);
        const float4* pfsrc = (const float4*)(x +
            (size_t)((pfv ? t2 : 0) / 6) * NREAL * CDIM + ((pfv ? t2 : 0) % 6) * MC);

        // Re-zero Pb's X pad rows (T of the tile before last clobbered them).
        if (pfv) {
            unsigned long long* pz = (unsigned long long*)(Pb + NREAL * XPITCHB);
            for (int i = tid; i < (KPAD - NREAL) * XPITCHB / 8; i += 256) pz[i] = 0ull;
        }

        float acc[2][13][4];
        #pragma unroll
        for (int mt = 0; mt < 2; mt++)
            #pragma unroll
            for (int nt = 0; nt < 13; nt++)
                #pragma unroll
                for (int j = 0; j < 4; j++) acc[mt][nt][j] = 0.f;

        // ---- GEMM1: C1[c][kdct] = X^T x B1 (trans A from X[n][c]); prefetch chunks 0..12 ----
        {
            const uint32_t aB  = sPa + (uint32_t)(kk * XPITCHB) + (uint32_t)((cw + g8) * 2);
            const uint32_t bB  = sB + (uint32_t)(lr * (BPITCH * 2)) + (uint32_t)((nbase + lc * 8) * 2);
            const uint32_t bB2 = sB + (uint32_t)(lr * (BPITCH * 2)) + (uint32_t)((nbase + 96) * 2);
            #pragma unroll 1
            for (int ks = 0; ks < KSTEPS; ks++) {
                const int pfi = ks * 256 + tid;
                const bool ld = pfv && (pfi < NF4);
                float4 v;
                if (ld) v = pfsrc[(pfi >> 5) * (CDIM / 4) + (pfi & 31)];

                const uint32_t kro = (uint32_t)(ks * 16 * XPITCHB);
                const uint32_t krb = (uint32_t)(ks * 16 * (BPITCH * 2));
                uint32_t a[2][4];
                #pragma unroll
                for (int mt = 0; mt < 2; mt++)
                    ldsm_x4t(aB + kro + (uint32_t)(mt * 32),
                             a[mt][0], a[mt][1], a[mt][2], a[mt][3]);
                uint32_t bf[13][2];
                #pragma unroll
                for (int p = 0; p < 6; p++)
                    ldsm_x4t(bB + krb + (uint32_t)(p * 32),
                             bf[2 * p][0], bf[2 * p][1], bf[2 * p + 1][0], bf[2 * p + 1][1]);
                ldsm_x2t(bB2 + krb, bf[12][0], bf[12][1]);
                #pragma unroll
                for (int mt = 0; mt < 2; mt++)
                    #pragma unroll
                    for (int nt = 0; nt < 13; nt++)
                        mma16816(acc[mt][nt], a[mt][0], a[mt][1], a[mt][2], a[mt][3],
                                 bf[nt][0], bf[nt][1]);

                if (ld) xstore(Pb, pfi, v);
            }
        }
        __syncthreads();

        // ---- mid: T[c][k] = fp16( C1 * g_wh2[c][k] ), T in Pa (pitch 432B) ----
        #pragma unroll
        for (int mt = 0; mt < 2; mt++) {
            const int r0 = cw + mt * 16 + grp;
            const int r1 = r0 + 8;
            #pragma unroll
            for (int nt = 0; nt < 13; nt++) {
                const int col = nbase + nt * 8 + q2;
                float2 w0 = __half22float2(*(const __half2*)&g_wh2[(c0 + r0) * WPITCH + col]);
                float2 w1 = __half22float2(*(const __half2*)&g_wh2[(c0 + r1) * WPITCH + col]);
                __half2 h0 = __floats2half2_rn(acc[mt][nt][0] * w0.x, acc[mt][nt][1] * w0.y);
                __half2 h1 = __floats2half2_rn(acc[mt][nt][2] * w1.x, acc[mt][nt][3] * w1.y);
                *(uint32_t*)(Pa + r0 * TPITCHB + col * 2) = *(uint32_t*)&h0;
                *(uint32_t*)(Pa + r1 * TPITCHB + col * 2) = *(uint32_t*)&h1;
            }
        }
        __syncthreads();

        #pragma unroll
        for (int mt = 0; mt < 2; mt++)
            #pragma unroll
            for (int nt = 0; nt < 13; nt++)
                #pragma unroll
                for (int j = 0; j < 4; j++) acc[mt][nt][j] = 0.f;

        // ---- GEMM2: C2[c][n] = T x B1^T (non-trans A,B); prefetch chunks 13..25 ----
        {
            const uint32_t aB  = sPa + (uint32_t)((cw + lr) * TPITCHB) + (uint32_t)(lc * 16);
            const uint32_t bB  = sB + (uint32_t)((nbase + kk) * (BPITCH * 2)) + (uint32_t)(g8 * 2);
            const uint32_t bB2 = sB + (uint32_t)((nbase + 96 + (lane & 7)) * (BPITCH * 2)) +
                                 (uint32_t)(g8 * 2);
            #pragma unroll 1
            for (int ks = 0; ks < KSTEPS; ks++) {
                const int pfi = (KSTEPS + ks) * 256 + tid;
                const bool ld = pfv && (pfi < NF4);
                float4 v;
                if (ld) v = pfsrc[(pfi >> 5) * (CDIM / 4) + (pfi & 31)];

                const uint32_t ko = (uint32_t)(ks * 32);
                uint32_t a[2][4];
                #pragma unroll
                for (int mt = 0; mt < 2; mt++)
                    ldsm_x4(aB + (uint32_t)(mt * 16 * TPITCHB) + ko,
                            a[mt][0], a[mt][1], a[mt][2], a[mt][3]);
                uint32_t bf[13][2];
                #pragma unroll
                for (int p = 0; p < 6; p++)
                    ldsm_x4(bB + (uint32_t)(p * 16 * (BPITCH * 2)) + ko,
                            bf[2 * p][0], bf[2 * p][1], bf[2 * p + 1][0], bf[2 * p + 1][1]);
                ldsm_x2(bB2 + ko, bf[12][0], bf[12][1]);
                #pragma unroll
                for (int mt = 0; mt < 2; mt++)
                    #pragma unroll
                    for (int nt = 0; nt < 13; nt++)
                        mma16816(acc[mt][nt], a[mt][0], a[mt][1], a[mt][2], a[mt][3],
                                 bf[nt][0], bf[nt][1]);

                if (ld) xstore(Pb, pfi, v);
            }
        }

        // ---- epilogue: y[b, n, c0 + c] = C2[c][n] ----
        {
            float* yb = y + (size_t)b * NREAL * CDIM + c0;
            #pragma unroll
            for (int mt = 0; mt < 2; mt++) {
                const int r0 = cw + mt * 16 + grp;
                const int r1 = r0 + 8;
                #pragma unroll
                for (int nt = 0; nt < 13; nt++) {
                    const int ncol = nbase + nt * 8 + q2;
                    if (ncol < NREAL) {
                        yb[(size_t)ncol * CDIM + r0]       = acc[mt][nt][0];
                        yb[(size_t)(ncol + 1) * CDIM + r0] = acc[mt][nt][1];
                        yb[(size_t)ncol * CDIM + r1]       = acc[mt][nt][2];
                        yb[(size_t)(ncol + 1) * CDIM + r1] = acc[mt][nt][3];
                    }
                }
            }
        }
        __syncthreads();   // T reads + prefetch stores complete before next tile
    }
}

extern "C" void kernel_launch(void* const* d_in, const int* in_sizes, int n_in,
                              void* d_out, int out_size) {
    const float* x = (const float*)d_in[0];  // [B, N, C] fp32
    const float* w = (const float*)d_in[1];  // [C, N]    fp32
    float* y = (float*)d_out;                // [B, N, C] fp32

    cudaFuncSetAttribute(dct_mma_kernel,
                         cudaFuncAttributeMaxDynamicSharedMemorySize, SMEM_TOTAL);

    setup_all<<<CDIM, WPITCH>>>(w);
    dct_mma_kernel<<<GRID, 256, SMEM_TOTAL>>>(x, y);
}

// round 6
// speedup vs baseline: 1.1440x; 1.1440x over previous
#include <cuda_runtime.h>
#include <cuda_fp16.h>
#include <stdint.h>

// Shapes (fixed): x [B=256, N=196, C=768], weight [C=768, N=196], y [B, N, C]
#define NREAL  196
#define CDIM   768
#define KPAD   208        // n and k_dct padded to 13*16
#define KSTEPS 13
#define MC     128        // channels per tile
#define NTILES 1536       // 256 batches * 6 channel-blocks
#define GRID   148        // persistent
#define NTHREADS 512      // 16 warps

#define XPITCHB 272       // X row pitch bytes (136 halfs; /16 odd -> conflict-free)
#define TPITCHB 432       // T row pitch bytes (216 halfs; /16 odd -> conflict-free)
#define BPITCH  200       // B1 pitch halfs (400B; /16 odd -> conflict-free)
#define WPITCH  208

#define SM_B1  0                      // 208*200*2 = 83,200
#define SM_P0  83200                  // 56,576 (X: 208x136 halfs; T: 128x216 halfs)
#define SM_P1  139776                 // 56,576
#define PBYTES 56576
#define SMEM_TOTAL 196352
#define NF4    6272                   // float4 per X tile (196 rows * 32)

__device__ __align__(16) __half g_B1[KPAD * BPITCH];   // B1[n][k] = 2*cos(pi*k*(2n+1)/(2N))
__device__ __align__(16) __half g_wh2[CDIM * WPITCH];  // w[c][k] * s_k, zero-padded

// ---------------- helpers ----------------
__device__ __forceinline__ uint32_t smem_u32(const void* p) {
    uint32_t a;
    asm("{ .reg .u64 t; cvta.to.shared.u64 t, %1; cvt.u32.u64 %0, t; }" : "=r"(a) : "l"(p));
    return a;
}
__device__ __forceinline__ void ldsm_x4(uint32_t addr, uint32_t& r0, uint32_t& r1,
                                        uint32_t& r2, uint32_t& r3) {
    asm volatile("ldmatrix.sync.aligned.m8n8.x4.shared.b16 {%0,%1,%2,%3}, [%4];"
                 : "=r"(r0), "=r"(r1), "=r"(r2), "=r"(r3) : "r"(addr));
}
__device__ __forceinline__ void ldsm_x2(uint32_t addr, uint32_t& r0, uint32_t& r1) {
    asm volatile("ldmatrix.sync.aligned.m8n8.x2.shared.b16 {%0,%1}, [%2];"
                 : "=r"(r0), "=r"(r1) : "r"(addr));
}
__device__ __forceinline__ void ldsm_x4t(uint32_t addr, uint32_t& r0, uint32_t& r1,
                                         uint32_t& r2, uint32_t& r3) {
    asm volatile("ldmatrix.sync.aligned.m8n8.x4.trans.shared.b16 {%0,%1,%2,%3}, [%4];"
                 : "=r"(r0), "=r"(r1), "=r"(r2), "=r"(r3) : "r"(addr));
}
__device__ __forceinline__ void ldsm_x2t(uint32_t addr, uint32_t& r0, uint32_t& r1) {
    asm volatile("ldmatrix.sync.aligned.m8n8.x2.trans.shared.b16 {%0,%1}, [%2];"
                 : "=r"(r0), "=r"(r1) : "r"(addr));
}
__device__ __forceinline__ void mma16816(float c[4], uint32_t a0, uint32_t a1, uint32_t a2,
                                         uint32_t a3, uint32_t b0, uint32_t b1) {
    asm volatile(
        "mma.sync.aligned.m16n8k16.row.col.f32.f16.f16.f32 "
        "{%0,%1,%2,%3}, {%4,%5,%6,%7}, {%8,%9}, {%0,%1,%2,%3};"
        : "+f"(c[0]), "+f"(c[1]), "+f"(c[2]), "+f"(c[3])
        : "r"(a0), "r"(a1), "r"(a2), "r"(a3), "r"(b0), "r"(b1));
}
__device__ __forceinline__ void xstore(char* dst, int pfi, float4 v) {
    __half2 h0 = __floats2half2_rn(v.x, v.y);
    __half2 h1 = __floats2half2_rn(v.z, v.w);
    uint2 u = make_uint2(*(uint32_t*)&h0, *(uint32_t*)&h1);
    *(uint2*)(dst + (pfi >> 5) * XPITCHB + (pfi & 31) * 8) = u;
}

// ---------------- fused setup ----------------
__global__ void setup_all(const float* __restrict__ w) {
    int r = blockIdx.x;    // 0..767
    int k = threadIdx.x;   // 0..207
    float s = (k == 0) ? (0.25f / NREAL) : ((k < NREAL) ? (0.5f / NREAL) : 0.f);
    float wv = (k < NREAL) ? w[(size_t)r * NREAL + k] : 0.f;
    g_wh2[r * WPITCH + k] = __float2half_rn(wv * s);
    if (r < KPAD && k < BPITCH) {
        float v = 0.f;
        if (r < NREAL && k < NREAL) {
            int rr = (k * (2 * r + 1)) % (4 * NREAL);
            v = 2.f * cospif((float)rr / (float)(2 * NREAL));
        }
        g_B1[r * BPITCH + k] = __float2half_rn(v);
    }
}

// ---------------- main persistent kernel ----------------
__global__ __launch_bounds__(NTHREADS, 1)
void dct_mma_kernel(const float* __restrict__ x, float* __restrict__ y) {
    extern __shared__ __align__(16) char smem[];
    const uint32_t sb = smem_u32(smem);
    const uint32_t sB = sb + SM_B1;
    const int tid = threadIdx.x;
    const int lane = tid & 31, wid = tid >> 5;
    const int mw = wid & 7;              // 8 M-groups of 16 channels
    const int nw = wid >> 3;             // 2 N-groups of 104
    const int cw = mw * 16;
    const int nbase = nw * 104;

    const int lr  = lane & 15;
    const int lc  = lane >> 4;
    const int kk  = (lane & 7) + ((lane >> 4) << 3);
    const int g8  = ((lane >> 3) & 1) << 3;
    const int grp = lane >> 2;
    const int q2  = (lane & 3) << 1;

    // One-time: copy B1, zero both P buffers (incl. X pad rows).
    {
        const float4* s1 = (const float4*)g_B1;
        float4* d1 = (float4*)(smem + SM_B1);
        for (int i = tid; i < (KPAD * BPITCH * 2) / 16; i += NTHREADS) d1[i] = s1[i];
        float4 z = make_float4(0.f, 0.f, 0.f, 0.f);
        float4* pz = (float4*)(smem + SM_P0);
        for (int i = tid; i < (2 * PBYTES) / 16; i += NTHREADS) pz[i] = z;
    }

    // Prologue: blocking load of first tile into P0.
    int t = blockIdx.x;
    __syncthreads();
    {
        const float4* xp = (const float4*)(x + (size_t)(t / 6) * NREAL * CDIM + (t % 6) * MC);
        char* dst = smem + SM_P0;
        for (int i = tid; i < NF4; i += NTHREADS)
            xstore(dst, i, xp[(i >> 5) * (CDIM / 4) + (i & 31)]);
    }
    __syncthreads();

    int it = 0;
    for (; t < NTILES; t += GRID, it ^= 1) {
        const int c0 = (t % 6) * MC;
        const int b  = t / 6;
        char* Pa = smem + (it ? SM_P1 : SM_P0);
        char* Pb = smem + (it ? SM_P0 : SM_P1);
        const uint32_t sPa = sb + (it ? SM_P1 : SM_P0);

        const int t2 = t + GRID;
        const bool pfv = (t2 < NTILES);
        const float4* pfsrc = (const float4*)(x +
            (size_t)((pfv ? t2 : 0) / 6) * NREAL * CDIM + ((pfv ? t2 : 0) % 6) * MC);

        // Re-zero Pb's X pad rows (T of the tile before last clobbered them).
        if (pfv) {
            unsigned long long* pz = (unsigned long long*)(Pb + NREAL * XPITCHB);
            for (int i = tid; i < (KPAD - NREAL) * XPITCHB / 8; i += NTHREADS) pz[i] = 0ull;
        }

        float acc[13][4];
        #pragma unroll
        for (int nt = 0; nt < 13; nt++)
            #pragma unroll
            for (int j = 0; j < 4; j++) acc[nt][j] = 0.f;

        // ---- GEMM1: C1[c][kdct] = X^T x B1 (trans A from X[n][c]); prefetch all next-X ----
        {
            const uint32_t aB  = sPa + (uint32_t)(kk * XPITCHB) + (uint32_t)((cw + g8) * 2);
            const uint32_t bB  = sB + (uint32_t)(lr * (BPITCH * 2)) + (uint32_t)((nbase + lc * 8) * 2);
            const uint32_t bB2 = sB + (uint32_t)(lr * (BPITCH * 2)) + (uint32_t)((nbase + 96) * 2);
            #pragma unroll 1
            for (int ks = 0; ks < KSTEPS; ks++) {
                const int pfi = ks * NTHREADS + tid;   // 13*512 >= 6272: all loads here
                const bool ld = pfv && (pfi < NF4);
                float4 v;
                if (ld) v = pfsrc[(pfi >> 5) * (CDIM / 4) + (pfi & 31)];

                const uint32_t kro = (uint32_t)(ks * 16 * XPITCHB);
                const uint32_t krb = (uint32_t)(ks * 16 * (BPITCH * 2));
                uint32_t a[4];
                ldsm_x4t(aB + kro, a[0], a[1], a[2], a[3]);
                uint32_t bf[13][2];
                #pragma unroll
                for (int p = 0; p < 6; p++)
                    ldsm_x4t(bB + krb + (uint32_t)(p * 32),
                             bf[2 * p][0], bf[2 * p][1], bf[2 * p + 1][0], bf[2 * p + 1][1]);
                ldsm_x2t(bB2 + krb, bf[12][0], bf[12][1]);
                #pragma unroll
                for (int nt = 0; nt < 13; nt++)
                    mma16816(acc[nt], a[0], a[1], a[2], a[3], bf[nt][0], bf[nt][1]);

                if (ld) xstore(Pb, pfi, v);
            }
        }
        __syncthreads();

        // ---- mid: T[c][k] = fp16( C1 * g_wh2[c][k] ), T in Pa (pitch 432B) ----
        {
            const int r0 = cw + grp;
            const int r1 = r0 + 8;
            #pragma unroll
            for (int nt = 0; nt < 13; nt++) {
                const int col = nbase + nt * 8 + q2;
                float2 w0 = __half22float2(*(const __half2*)&g_wh2[(c0 + r0) * WPITCH + col]);
                float2 w1 = __half22float2(*(const __half2*)&g_wh2[(c0 + r1) * WPITCH + col]);
                __half2 h0 = __floats2half2_rn(acc[nt][0] * w0.x, acc[nt][1] * w0.y);
                __half2 h1 = __floats2half2_rn(acc[nt][2] * w1.x, acc[nt][3] * w1.y);
                *(uint32_t*)(Pa + r0 * TPITCHB + col * 2) = *(uint32_t*)&h0;
                *(uint32_t*)(Pa + r1 * TPITCHB + col * 2) = *(uint32_t*)&h1;
            }
        }
        __syncthreads();

        #pragma unroll
        for (int nt = 0; nt < 13; nt++)
            #pragma unroll
            for (int j = 0; j < 4; j++) acc[nt][j] = 0.f;

        // ---- GEMM2: C2[c][n] = T x B1^T (non-trans A,B) ----
        {
            const uint32_t aB  = sPa + (uint32_t)((cw + lr) * TPITCHB) + (uint32_t)(lc * 16);
            const uint32_t bB  = sB + (uint32_t)((nbase + kk) * (BPITCH * 2)) + (uint32_t)(g8 * 2);
            const uint32_t bB2 = sB + (uint32_t)((nbase + 96 + (lane & 7)) * (BPITCH * 2)) +
                                 (uint32_t)(g8 * 2);
            #pragma unroll 1
            for (int ks = 0; ks < KSTEPS; ks++) {
                const uint32_t ko = (uint32_t)(ks * 32);
                uint32_t a[4];
                ldsm_x4(aB + ko, a[0], a[1], a[2], a[3]);
                uint32_t bf[13][2];
                #pragma unroll
                for (int p = 0; p < 6; p++)
                    ldsm_x4(bB + (uint32_t)(p * 16 * (BPITCH * 2)) + ko,
                            bf[2 * p][0], bf[2 * p][1], bf[2 * p + 1][0], bf[2 * p + 1][1]);
                ldsm_x2(bB2 + ko, bf[12][0], bf[12][1]);
                #pragma unroll
                for (int nt = 0; nt < 13; nt++)
                    mma16816(acc[nt], a[0], a[1], a[2], a[3], bf[nt][0], bf[nt][1]);
            }
        }

        // ---- epilogue: y[b, n, c0 + c] = C2[c][n] ----
        {
            float* yb = y + (size_t)b * NREAL * CDIM + c0;
            const int r0 = cw + grp;
            const int r1 = r0 + 8;
            #pragma unroll
            for (int nt = 0; nt < 13; nt++) {
                const int ncol = nbase + nt * 8 + q2;
                if (ncol < NREAL) {
                    yb[(size_t)ncol * CDIM + r0]       = acc[nt][0];
                    yb[(size_t)(ncol + 1) * CDIM + r0] = acc[nt][1];
                    yb[(size_t)ncol * CDIM + r1]       = acc[nt][2];
                    yb[(size_t)(ncol + 1) * CDIM + r1] = acc[nt][3];
                }
            }
        }
        __syncthreads();   // T reads + prefetch stores complete before next tile
    }
}

extern "C" void kernel_launch(void* const* d_in, const int* in_sizes, int n_in,
                              void* d_out, int out_size) {
    const float* x = (const float*)d_in[0];  // [B, N, C] fp32
    const float* w = (const float*)d_in[1];  // [C, N]    fp32
    float* y = (float*)d_out;                // [B, N, C] fp32

    cudaFuncSetAttribute(dct_mma_kernel,
                         cudaFuncAttributeMaxDynamicSharedMemorySize, SMEM_TOTAL);

    setup_all<<<CDIM, WPITCH>>>(w);
    dct_mma_kernel<<<GRID, NTHREADS, SMEM_TOTAL>>>(x, y);
}